// round 5
// baseline (speedup 1.0000x reference)
#include <cuda_runtime.h>
#include <math_constants.h>

// DarkChannel fused, producer/consumer pipelined:
//   Group A (warps 0-4): channel-min(C=3) + vertical 15-min (van Herk, float2)
//                        -> eroded tile in smem buffer (double-buffered)
//   Group B (warps 5-8): horizontal 15-min from smem -> out
// Each block walks K_TILES consecutive y-tiles; A fills tile e while B drains
// tile e-1, so DRAM loads stay in flight through the whole block lifetime.
//
// img [16,3,1024,1024] f32 -> out [16,1,1024,1024] f32, +inf border erosion.

#define IMG_H 1024
#define IMG_W 1024
#define IMG_B 16
#define CH_STRIDE (IMG_H * IMG_W)
#define YTILE 15
#define NUM_TY 69                     // ceil(1024/15)
#define XSPAN 256
#define HALO 8
#define SROW (XSPAN + 2 * HALO)       // 272
#define K_TILES 6
#define NA 160                        // group A threads (136 active)
#define NB 128                        // group B threads
#define NTHREADS (NA + NB)            // 288

__device__ __forceinline__ float2 min2(float2 a, float2 b) {
    return make_float2(fminf(a.x, b.x), fminf(a.y, b.y));
}

template <bool CHECKY>
__device__ __forceinline__ float2 cmin2(const float* p, int y, bool vx) {
    if (!vx || (CHECKY && (unsigned)y >= (unsigned)IMG_H)) {
        return make_float2(CUDART_INF_F, CUDART_INF_F);
    }
    const float* r = p + (size_t)y * IMG_W;
    float2 c0 = *reinterpret_cast<const float2*>(r);
    float2 c1 = *reinterpret_cast<const float2*>(r + CH_STRIDE);
    float2 c2 = *reinterpret_cast<const float2*>(r + 2 * CH_STRIDE);
    return min2(min2(c0, c1), c2);
}

// Vertical van Herk (block == window == 15) for one float2 column pair.
// Writes 15 eroded rows into smem at stride SROW.
template <bool CHECKY>
__device__ __forceinline__ void vert(const float* p, bool vx, int y0, float* s) {
    float2 h[YTILE];
#pragma unroll
    for (int t = 0; t < YTILE; ++t) {
        h[t] = cmin2<CHECKY>(p, y0 - 7 + t, vx);       // rows y0-7 .. y0+7
    }
#pragma unroll
    for (int t = YTILE - 2; t >= 0; --t) {
        h[t] = min2(h[t], h[t + 1]);                   // suffix mins
    }

    *reinterpret_cast<float2*>(&s[0]) = h[0];

    float2 g = make_float2(CUDART_INF_F, CUDART_INF_F);
#pragma unroll
    for (int r = 1; r < YTILE; ++r) {
        g = min2(g, cmin2<CHECKY>(p, y0 + 7 + r, vx)); // next-block prefix
        *reinterpret_cast<float2*>(&s[r * SROW]) = min2(h[r], g);
    }
}

extern "C" __global__ __launch_bounds__(NTHREADS, 4)
void k_fused(const float* __restrict__ img, float* __restrict__ out) {
    __shared__ float buf[2][YTILE * SROW];             // 2 x 16320 B

    const int tid = threadIdx.x;
    const int bx  = blockIdx.x;                        // x strip 0..3
    const int ty0 = blockIdx.y * K_TILES;              // first y-tile of this block
    const int b   = blockIdx.z;
    const int X0  = bx * XSPAN;

    const float* imgb = img + (size_t)b * 3 * CH_STRIDE;
    float* outb = out + (size_t)b * IMG_H * IMG_W;

    for (int e = 0; e <= K_TILES; ++e) {
        if (tid < NA) {
            // ---- Group A: fill tile (ty0+e) into buf[e&1] ----
            const int ty = ty0 + e;
            const int lc = tid << 1;
            if (e < K_TILES && ty < NUM_TY && lc < SROW) {
                const int y0 = ty * YTILE;
                const int gx = X0 - HALO + lc;
                const bool vx = (unsigned)gx < (unsigned)IMG_W;
                const float* p = imgb + gx;
                float* s = &buf[e & 1][lc];
                if (ty >= 1 && ty <= 66) {
                    vert<false>(p, vx, y0, s);
                } else {
                    vert<true>(p, vx, y0, s);
                }
            }
        } else {
            // ---- Group B: drain tile (ty0+e-1) from buf[(e-1)&1] ----
            const int ty = ty0 + e - 1;
            if (e >= 1 && ty < NUM_TY) {
                const int y0 = ty * YTILE;
                const int vrows = min(YTILE, IMG_H - y0);
                const float* B = buf[(e - 1) & 1];
                const int bt = tid - NA;

                for (int i = bt; i < 64 * vrows; i += NB) {
                    const int r = i >> 6;
                    const int c = i & 63;
                    const float* row = &B[r * SROW];
                    const int L0 = (c << 2) + HALO;

                    float f[20];
#pragma unroll
                    for (int q = 0; q < 5; ++q) {
                        float4 v = *reinterpret_cast<const float4*>(&row[L0 - 8 + 4 * q]);
                        f[q * 4 + 0] = v.x;
                        f[q * 4 + 1] = v.y;
                        f[q * 4 + 2] = v.z;
                        f[q * 4 + 3] = v.w;
                    }

                    float core = f[4];
#pragma unroll
                    for (int k = 5; k <= 15; ++k) core = fminf(core, f[k]);

                    float p23   = fminf(f[2], f[3]);
                    float p1617 = fminf(f[16], f[17]);

                    float4 o;
                    o.x = fminf(core, fminf(f[1], p23));
                    o.y = fminf(core, fminf(p23, f[16]));
                    o.z = fminf(core, fminf(f[3], p1617));
                    o.w = fminf(core, fminf(p1617, f[18]));

                    float* op = outb + (size_t)(y0 + r) * IMG_W + X0 + (c << 2);
                    *reinterpret_cast<float4*>(op) = o;
                }
            }
        }
        __syncthreads();
    }
}

extern "C" void kernel_launch(void* const* d_in, const int* in_sizes, int n_in,
                              void* d_out, int out_size) {
    const float* img = (const float*)d_in[0];
    float* out = (float*)d_out;

    dim3 grid(IMG_W / XSPAN, (NUM_TY + K_TILES - 1) / K_TILES, IMG_B);  // 4 x 12 x 16
    k_fused<<<grid, NTHREADS>>>(img, out);
}